// round 8
// baseline (speedup 1.0000x reference)
#include <cuda_runtime.h>
#include <cuda_bf16.h>
#include <mma.h>
#include <math.h>
#include <cstdint>

using namespace nvcuda;

#define N 1024
#define E 128
#define NEG 0.2f

#define I_PER_CTA 8
#define BMJ 64                    // j-rows per CTA
#define LDA_H 136                 // bf16 elements per padded row (272 B)
#define LDC 132                   // fp32 C stride
// smem byte offsets
#define OFF_A0 0
#define OFF_A1 17408
#define OFF_B  34816
#define OFF_C  69632
#define OFF_W  103424
#define SMEM_DYN (OFF_W + 512 + 64)

// ---- scratch ----
__device__ float g_wf[N * E];
__device__ float g_base[N * E];
__device__ float g_s[N];
__device__ float g_wa2[E];
__device__ float g_logits[(size_t)N * N];
__device__ __nv_bfloat16 g_Bb[E * E];   // pc_Wp in bf16, [k][n] row-major

__device__ __forceinline__ float lrelu(float x) { return fmaxf(x, NEG * x); }

// ---------------- small precompute kernels ----------------
__global__ void k_wf(const float* __restrict__ embs, const float* __restrict__ W) {
    __shared__ float es[E];
    int i = blockIdx.x, l = threadIdx.x;
    es[l] = embs[i * E + l];
    __syncthreads();
    float acc = 0.f;
#pragma unroll 8
    for (int k = 0; k < E; k++) acc = fmaf(es[k], W[k * E + l], acc);
    g_wf[i * E + l] = acc;
}

__global__ void k_wa2(const float* __restrict__ W, const float* __restrict__ aW) {
    __shared__ float a2s[E];
    int m = threadIdx.x;
    a2s[m] = aW[E + m];
    __syncthreads();
    float acc = 0.f;
#pragma unroll 8
    for (int k = 0; k < E; k++) acc = fmaf(W[m * E + k], a2s[k], acc);
    g_wa2[m] = acc;
}

__global__ void k_base(const float* __restrict__ pcW, const float* __restrict__ pcb,
                       const float* __restrict__ aW) {
    __shared__ float ws[E];
    __shared__ float red[E];
    int i = blockIdx.x, l = threadIdx.x;
    float w = g_wf[i * E + l];
    ws[l] = w;
    red[l] = w * aW[l];
    __syncthreads();
    float acc = pcb[l];
#pragma unroll 8
    for (int k = 0; k < E; k++) acc = fmaf(ws[k], pcW[k * E + l], acc);
    g_base[i * E + l] = acc;
    for (int off = 64; off > 0; off >>= 1) {
        __syncthreads();
        if (l < off) red[l] += red[l + off];
    }
    __syncthreads();
    if (l == 0) g_s[i] = red[0];
}

// g_Bb[k][n] = bf16(pc_Wp[k][n])
__global__ void k_bb(const float* __restrict__ pcW) {
    int idx = blockIdx.x * 128 + threadIdx.x;
    g_Bb[idx] = __float2bfloat16(pcW[E * E + idx]);
}

// ---------------- bf16 wmma big kernel (64x128 tiles, 2 CTAs/SM) ----------------
// grid (16, 128): blockIdx.x = 64-row j-block, blockIdx.y = i-chunk (8 i's).
__global__ void __launch_bounds__(256, 2)
k_big(const float* __restrict__ pde, const int* __restrict__ adj,
      const float* __restrict__ ab_ptr) {
    extern __shared__ char sm[];
    __nv_bfloat16* Ab[2] = { (__nv_bfloat16*)(sm + OFF_A0), (__nv_bfloat16*)(sm + OFF_A1) };
    __nv_bfloat16* Bb = (__nv_bfloat16*)(sm + OFF_B);
    float* Cs = (float*)(sm + OFF_C);
    float* wa2s = (float*)(sm + OFF_W);

    const int tid = threadIdx.x;
    const int wid = tid >> 5;
    const int j0 = blockIdx.x * BMJ;
    const int i_base = blockIdx.y * I_PER_CTA;
    const float ab = ab_ptr[0];

    // ---- prologue: B (bf16 copy) + A0 (fp32->bf16) + wa2 ----
#pragma unroll
    for (int t = 0; t < 8; t++) {
        int idx = tid + t * 256;               // 2048 chunks of 8 bf16
        int row = idx >> 4, c8 = (idx & 15) * 8;
        *(uint4*)(Bb + row * LDA_H + c8) = *(const uint4*)(g_Bb + row * E + c8);
    }
    {
        const float* gA = pde + ((size_t)i_base * N + j0) * E;
#pragma unroll
        for (int t = 0; t < 4; t++) {
            int idx = tid + t * 256;           // 1024 chunks of 8 floats
            int row = idx >> 4, c8 = (idx & 15) * 8;
            const float4* g = (const float4*)(gA + (size_t)row * E + c8);
            float4 v0 = g[0], v1 = g[1];
            __nv_bfloat162 p0 = __floats2bfloat162_rn(v0.x, v0.y);
            __nv_bfloat162 p1 = __floats2bfloat162_rn(v0.z, v0.w);
            __nv_bfloat162 p2 = __floats2bfloat162_rn(v1.x, v1.y);
            __nv_bfloat162 p3 = __floats2bfloat162_rn(v1.z, v1.w);
            uint4 o;
            o.x = *(uint32_t*)&p0; o.y = *(uint32_t*)&p1;
            o.z = *(uint32_t*)&p2; o.w = *(uint32_t*)&p3;
            *(uint4*)(Ab[0] + row * LDA_H + c8) = o;
        }
    }
    if (tid < E) wa2s[tid] = g_wa2[tid];
    __syncthreads();

    const int wr = (wid & 1) * 32;    // warp row base (0/32)
    const int wc = (wid >> 1) * 32;   // warp col base (0..96)

    for (int s = 0; s < I_PER_CTA; s++) {
        __nv_bfloat16* A = Ab[s & 1];

        // 1) issue LDG for next A tile into regs (latency overlaps epilogue+mma)
        float4 stage[8];
        if (s + 1 < I_PER_CTA) {
            const float* gA = pde + ((size_t)(i_base + s + 1) * N + j0) * E;
#pragma unroll
            for (int t = 0; t < 4; t++) {
                int idx = tid + t * 256;
                int row = idx >> 4, c8 = (idx & 15) * 8;
                const float4* g = (const float4*)(gA + (size_t)row * E + c8);
                stage[2 * t] = g[0];
                stage[2 * t + 1] = g[1];
            }
        }

        // 2) epilogue for tile s-1 (C in Cs, synced at end of prev iter)
        if (s > 0) {
            const int i = i_base + s - 1;
            const int row = tid >> 2, q = tid & 3;
            const float* cr = Cs + row * LDC + q * 32;
            const float* br = g_base + (size_t)(j0 + row) * E + q * 32;
            const float* w2 = wa2s + q * 32;
            float part = 0.f;
#pragma unroll
            for (int c = 0; c < 32; c += 4) {
                float4 cv = *(const float4*)(cr + c);
                float4 bv = *(const float4*)(br + c);
                part = fmaf(lrelu(cv.x + bv.x), w2[c], part);
                part = fmaf(lrelu(cv.y + bv.y), w2[c + 1], part);
                part = fmaf(lrelu(cv.z + bv.z), w2[c + 2], part);
                part = fmaf(lrelu(cv.w + bv.w), w2[c + 3], part);
            }
            part += __shfl_xor_sync(0xffffffffu, part, 1);
            part += __shfl_xor_sync(0xffffffffu, part, 2);
            if (q == 0) {
                float lg = lrelu(g_s[i] + part + ab);
                size_t oidx = (size_t)i * N + j0 + row;
                g_logits[oidx] = (adj[oidx] == 1) ? lg : -1e30f;
            }
        }

        // 3) bf16 wmma: 64x128x128, warp tile 32x32
        wmma::fragment<wmma::accumulator, 16, 16, 16, float> fc[2][2];
#pragma unroll
        for (int r = 0; r < 2; r++)
#pragma unroll
            for (int c = 0; c < 2; c++) wmma::fill_fragment(fc[r][c], 0.f);

#pragma unroll
        for (int ks = 0; ks < 8; ks++) {
            const int k0 = ks * 16;
            wmma::fragment<wmma::matrix_a, 16, 16, 16, __nv_bfloat16, wmma::row_major> fa[2];
            wmma::fragment<wmma::matrix_b, 16, 16, 16, __nv_bfloat16, wmma::row_major> fb[2];
#pragma unroll
            for (int r = 0; r < 2; r++)
                wmma::load_matrix_sync(fa[r], A + (wr + r * 16) * LDA_H + k0, LDA_H);
#pragma unroll
            for (int c = 0; c < 2; c++)
                wmma::load_matrix_sync(fb[c], Bb + k0 * LDA_H + wc + c * 16, LDA_H);
#pragma unroll
            for (int r = 0; r < 2; r++)
#pragma unroll
                for (int c = 0; c < 2; c++)
                    wmma::mma_sync(fc[r][c], fa[r], fb[c], fc[r][c]);
        }

        // 4) all threads past epilogue reads of Cs and A reads
        __syncthreads();

        // 5) store C frags; STS staged A[s+1]
#pragma unroll
        for (int r = 0; r < 2; r++)
#pragma unroll
            for (int c = 0; c < 2; c++)
                wmma::store_matrix_sync(Cs + (wr + r * 16) * LDC + wc + c * 16,
                                        fc[r][c], LDC, wmma::mem_row_major);
        if (s + 1 < I_PER_CTA) {
            __nv_bfloat16* dst = Ab[1 - (s & 1)];
#pragma unroll
            for (int t = 0; t < 4; t++) {
                int idx = tid + t * 256;
                int row = idx >> 4, c8 = (idx & 15) * 8;
                float4 v0 = stage[2 * t], v1 = stage[2 * t + 1];
                __nv_bfloat162 p0 = __floats2bfloat162_rn(v0.x, v0.y);
                __nv_bfloat162 p1 = __floats2bfloat162_rn(v0.z, v0.w);
                __nv_bfloat162 p2 = __floats2bfloat162_rn(v1.x, v1.y);
                __nv_bfloat162 p3 = __floats2bfloat162_rn(v1.z, v1.w);
                uint4 o;
                o.x = *(uint32_t*)&p0; o.y = *(uint32_t*)&p1;
                o.z = *(uint32_t*)&p2; o.w = *(uint32_t*)&p3;
                *(uint4*)(dst + row * LDA_H + c8) = o;
            }
        }
        __syncthreads();
    }

    // final epilogue: tile 7
    {
        const int i = i_base + I_PER_CTA - 1;
        const int row = tid >> 2, q = tid & 3;
        const float* cr = Cs + row * LDC + q * 32;
        const float* br = g_base + (size_t)(j0 + row) * E + q * 32;
        const float* w2 = wa2s + q * 32;
        float part = 0.f;
#pragma unroll
        for (int c = 0; c < 32; c += 4) {
            float4 cv = *(const float4*)(cr + c);
            float4 bv = *(const float4*)(br + c);
            part = fmaf(lrelu(cv.x + bv.x), w2[c], part);
            part = fmaf(lrelu(cv.y + bv.y), w2[c + 1], part);
            part = fmaf(lrelu(cv.z + bv.z), w2[c + 2], part);
            part = fmaf(lrelu(cv.w + bv.w), w2[c + 3], part);
        }
        part += __shfl_xor_sync(0xffffffffu, part, 1);
        part += __shfl_xor_sync(0xffffffffu, part, 2);
        if (q == 0) {
            float lg = lrelu(g_s[i] + part + ab);
            size_t oidx = (size_t)i * N + j0 + row;
            g_logits[oidx] = (adj[oidx] == 1) ? lg : -1e30f;
        }
    }
}

// ---------------- softmax + attn@embs + concat ----------------
#define RPB 4
__global__ void __launch_bounds__(128)
k_out(const float* __restrict__ embs, float* __restrict__ out) {
    __shared__ float attn[RPB][N];
    __shared__ float red[E];
    const int i0 = blockIdx.x * RPB;
    const int t = threadIdx.x;

    float inv[RPB];
#pragma unroll
    for (int r = 0; r < RPB; r++) {
        const float* lg = g_logits + (size_t)(i0 + r) * N;
        float m = -1e30f;
#pragma unroll
        for (int q = 0; q < N / E; q++) m = fmaxf(m, lg[t + q * E]);
        red[t] = m;
        for (int off = 64; off > 0; off >>= 1) {
            __syncthreads();
            if (t < off) red[t] = fmaxf(red[t], red[t + off]);
        }
        __syncthreads();
        m = red[0];
        __syncthreads();
        float s = 0.f;
#pragma unroll
        for (int q = 0; q < N / E; q++) {
            float e = expf(lg[t + q * E] - m);
            attn[r][t + q * E] = e;
            s += e;
        }
        red[t] = s;
        for (int off = 64; off > 0; off >>= 1) {
            __syncthreads();
            if (t < off) red[t] += red[t + off];
        }
        __syncthreads();
        inv[r] = 1.f / red[0];
        __syncthreads();
    }

    float acc[RPB];
#pragma unroll
    for (int r = 0; r < RPB; r++) acc[r] = 0.f;
#pragma unroll 8
    for (int j = 0; j < N; j++) {
        float ev = embs[j * E + t];
#pragma unroll
        for (int r = 0; r < RPB; r++) acc[r] = fmaf(attn[r][j], ev, acc[r]);
    }
#pragma unroll
    for (int r = 0; r < RPB; r++) {
        int i = i0 + r;
        out[(size_t)i * (2 * E) + t] = embs[i * E + t];
        out[(size_t)i * (2 * E) + E + t] = acc[r] * inv[r];
    }
}

// ---------------- launch ----------------
extern "C" void kernel_launch(void* const* d_in, const int* in_sizes, int n_in,
                              void* d_out, int out_size) {
    const float* embs = (const float*)d_in[0];
    const int*   adj  = (const int*)d_in[1];
    const float* pde  = (const float*)d_in[2];
    const float* W    = (const float*)d_in[3];
    const float* pcW  = (const float*)d_in[4];
    const float* pcb  = (const float*)d_in[5];
    const float* aW   = (const float*)d_in[6];
    const float* ab   = (const float*)d_in[7];
    float* out = (float*)d_out;

    cudaFuncSetAttribute(k_big, cudaFuncAttributeMaxDynamicSharedMemorySize,
                         (int)SMEM_DYN);

    k_wf<<<N, E>>>(embs, W);
    k_wa2<<<1, E>>>(W, aW);
    k_base<<<N, E>>>(pcW, pcb, aW);
    k_bb<<<E, E>>>(pcW);
    k_big<<<dim3(N / BMJ, N / I_PER_CTA), 256, SMEM_DYN>>>(pde, adj, ab);
    k_out<<<N / RPB, 128>>>(embs, out);
}